// round 15
// baseline (speedup 1.0000x reference)
#include <cuda_runtime.h>
#include <cstdint>

#define NNODE 50000
#define NEDGE 1600000

typedef unsigned long long ull;

// ---------------- device scratch (no allocations allowed) ----------------
__device__ float g_e1[(size_t)NEDGE * 32];   // lrelu(e1)
__device__ float g_e2[(size_t)NEDGE * 32];   // lrelu(e2)
__device__ float g_n1[(size_t)NNODE * 32];
__device__ float g_n2[(size_t)NNODE * 32];
__device__ float g_ns1[(size_t)NNODE * 32];
__device__ float g_ns2[(size_t)NNODE * 32];
__device__ float g_ns3[(size_t)NNODE * 32];
__device__ float g_inv[NNODE];
__device__ int   g_cnt[NNODE];

__device__ __forceinline__ float lrelu(float x) { return x > 0.f ? x : 0.2f * x; }

__device__ __forceinline__ ull bcast2(float v) {
    ull r; unsigned u = __float_as_uint(v);
    asm("mov.b64 %0, {%1,%1};" : "=l"(r) : "r"(u));
    return r;
}
__device__ __forceinline__ void unpack2(ull v, float& a, float& b) {
    unsigned lo, hi;
    asm("mov.b64 {%0,%1}, %2;" : "=r"(lo), "=r"(hi) : "l"(v));
    a = __uint_as_float(lo); b = __uint_as_float(hi);
}

// dual-edge, 16-output packed accumulate: one weight LDS.128 feeds 4 FFMA2
__device__ __forceinline__ void fma8p2(ull (&accA)[8], ull (&accB)[8],
                                       ull hA, ull hB,
                                       const float* __restrict__ wrow) {
    const ulonglong2* w = (const ulonglong2*)wrow;
#pragma unroll
    for (int j = 0; j < 4; j++) {
        ulonglong2 wv = w[j];
        asm("fma.rn.f32x2 %0, %1, %2, %0;" : "+l"(accA[2 * j + 0]) : "l"(hA), "l"(wv.x));
        asm("fma.rn.f32x2 %0, %1, %2, %0;" : "+l"(accB[2 * j + 0]) : "l"(hB), "l"(wv.x));
        asm("fma.rn.f32x2 %0, %1, %2, %0;" : "+l"(accA[2 * j + 1]) : "l"(hA), "l"(wv.y));
        asm("fma.rn.f32x2 %0, %1, %2, %0;" : "+l"(accB[2 * j + 1]) : "l"(hB), "l"(wv.y));
    }
}

// 4 consecutive k-steps, vectorized h (both edges) against weight rows
__device__ __forceinline__ void fma8p2_k4(ull (&accA)[8], ull (&accB)[8],
                                          float4 hA4, float4 hB4,
                                          const float* __restrict__ wbase /* row k0, +32/step */) {
    float hA[4] = { hA4.x, hA4.y, hA4.z, hA4.w };
    float hB[4] = { hB4.x, hB4.y, hB4.z, hB4.w };
#pragma unroll
    for (int q = 0; q < 4; q++)
        fma8p2(accA, accB, bcast2(hA[q]), bcast2(hB[q]), wbase + q * 32);
}

// single-edge 32-output version (node kernel)
__device__ __forceinline__ void fma16p(ull (&acc)[16], ull h2, const float* __restrict__ wrow) {
    const ulonglong2* w = (const ulonglong2*)wrow;
#pragma unroll
    for (int j = 0; j < 8; j++) {
        ulonglong2 wv = w[j];
        asm("fma.rn.f32x2 %0, %1, %2, %0;" : "+l"(acc[2 * j + 0]) : "l"(h2), "l"(wv.x));
        asm("fma.rn.f32x2 %0, %1, %2, %0;" : "+l"(acc[2 * j + 1]) : "l"(h2), "l"(wv.y));
    }
}

// ---------------- setup kernels ----------------
__global__ void zero_kernel() {
    int stride = gridDim.x * blockDim.x;
    int i0 = blockIdx.x * blockDim.x + threadIdx.x;
    for (int v = i0; v < NNODE * 32; v += stride) {
        g_ns1[v] = 0.f; g_ns2[v] = 0.f; g_ns3[v] = 0.f;
    }
    for (int v = i0; v < NNODE; v += stride) g_cnt[v] = 0;
}

__global__ void count_kernel(const int* __restrict__ row) {
    int e = blockIdx.x * 256 + threadIdx.x;
    atomicAdd(&g_cnt[row[e]], 1);
}

__global__ void inv_kernel() {
    int v = blockIdx.x * 256 + threadIdx.x;
    if (v < NNODE) g_inv[v] = 1.f / fmaxf((float)g_cnt[v], 1.f);
}

// ---------------- fused edge-conv kernel ----------------
// 128 threads/block, 128 edges/block -> up to 6 blocks/SM for deep
// inter-block phase overlap (gather phases of one block hide under FMA
// phases of others).
// Thread layout: g = tid>>6 selects output half [g*16, g*16+16);
//                eA = tid&63, eB = eA+64 are the two edges this thread owns.
template <int CIN, bool FUSE_MLP>
__global__ __launch_bounds__(128, 6)
void conv_kernel(const float* __restrict__ xn,
                 const float* __restrict__ ef0,
                 const float* __restrict__ ef1,
                 const float* __restrict__ ef2,
                 const int* __restrict__ ridx,
                 const int* __restrict__ cidx,
                 const float* __restrict__ w1, const float* __restrict__ b1,
                 const float* __restrict__ w2, const float* __restrict__ b2,
                 const float* __restrict__ mw1, const float* __restrict__ mb1,
                 const float* __restrict__ mw2, const float* __restrict__ mb2,
                 const float* __restrict__ mw3, const float* __restrict__ mb3,
                 float* __restrict__ nsum,
                 float* __restrict__ eout) {
    constexpr int NB = CIN / 32;
    constexpr int SP = 36;                 // floats per edge row (float4-aligned, conflict-free)
    constexpr int MSZ = FUSE_MLP ? 3168 : 0;
    extern __shared__ float sm[];
    float* cs  = sm;                       // 128 * 36
    float* w1s = sm + 128 * SP;            // CIN*32 (16B aligned)
    float* w2s = w1s + CIN * 32;           // 1024
    float* b1s = w2s + 1024;               // 32
    float* b2s = b1s + 32;                 // 32
    float* ms  = b2s + 32;                 // fused MLP weights
    int*   rs  = (int*)(ms + MSZ);         // 128
    int*   cls = rs + 128;                 // 128

    const int tid = threadIdx.x;           // 0..127
    const int g   = tid >> 6;              // output half
    const int go  = g * 16;                // output offset
    const int eA  = tid & 63;
    const int eB  = eA + 64;
    const size_t tile0 = (size_t)blockIdx.x * 128;

    // stage weights + this block's indices
    for (int v = tid; v < CIN * 32; v += 128) w1s[v] = w1[v];
    for (int v = tid; v < 1024; v += 128)     w2s[v] = w2[v];
    if (tid < 32) { b1s[tid] = b1[tid]; b2s[tid] = b2[tid]; }
    if constexpr (FUSE_MLP) {
        for (int v = tid; v < 1024; v += 128) {
            ms[v] = mw1[v]; ms[1056 + v] = mw2[v]; ms[2112 + v] = mw3[v];
        }
        if (tid < 32) { ms[1024 + tid] = mb1[tid]; ms[2080 + tid] = mb2[tid]; ms[3136 + tid] = mb3[tid]; }
    }
    rs[tid]  = ridx[tile0 + tid];
    cls[tid] = cidx[tile0 + tid];
    __syncthreads();

    const int rA = rs[eA];
    const int rB = rs[eB];

    ull accA[8], accB[8];
    {
        const ull* bp = (const ull*)(b1s + go);
#pragma unroll
        for (int j = 0; j < 8; j++) { accA[j] = bp[j]; accB[j] = bp[j]; }
    }

    const float* efp[3] = { ef0, ef1, ef2 };

    for (int b = 0; b < NB; b++) {
        if (b > 0) __syncthreads();        // compute of b-1 done before restaging cs
        if (b < 2) {
            // warp-coalesced gather: one 128B node row -> one edge row in cs
            const int* sidx = (b == 0) ? rs : cls;
            const int ch = tid & 31;
            const int e0 = tid >> 5;       // 0..3 (4 warps)
#pragma unroll
            for (int it = 0; it < 32; it++) {
                int eidx = e0 + it * 4;
                cs[eidx * SP + ch] = xn[(size_t)sidx[eidx] * 32 + ch];
            }
        } else {
            // direct float4 copy of 128x32 edge-feature chunk (edge-major)
            const float4* src = (const float4*)(efp[b - 2] + tile0 * 32);
#pragma unroll
            for (int it = 0; it < 8; it++) {
                int v = tid + it * 128;
                int eidx = v >> 3;
                int ch = (v & 7) * 4;
                *(float4*)(cs + eidx * SP + ch) = src[v];
            }
        }
        __syncthreads();
#pragma unroll
        for (int k4 = 0; k4 < 8; k4++) {
            float4 hA4 = *(const float4*)(cs + eA * SP + 4 * k4);
            float4 hB4 = *(const float4*)(cs + eB * SP + 4 * k4);
            fma8p2_k4(accA, accB, hA4, hB4, &w1s[(b * 32 + 4 * k4) * 32 + go]);
        }
    }

    // stage relu(hidden): thread writes cols [go,go+16) of its two edge rows
    __syncthreads();
    {
        float h[16];
#pragma unroll
        for (int j = 0; j < 8; j++) {
            float a0, a1; unpack2(accA[j], a0, a1);
            h[2 * j] = fmaxf(a0, 0.f); h[2 * j + 1] = fmaxf(a1, 0.f);
        }
#pragma unroll
        for (int j4 = 0; j4 < 4; j4++)
            *(float4*)(cs + eA * SP + go + 4 * j4) =
                make_float4(h[4 * j4], h[4 * j4 + 1], h[4 * j4 + 2], h[4 * j4 + 3]);
#pragma unroll
        for (int j = 0; j < 8; j++) {
            float a0, a1; unpack2(accB[j], a0, a1);
            h[2 * j] = fmaxf(a0, 0.f); h[2 * j + 1] = fmaxf(a1, 0.f);
        }
#pragma unroll
        for (int j4 = 0; j4 < 4; j4++)
            *(float4*)(cs + eB * SP + go + 4 * j4) =
                make_float4(h[4 * j4], h[4 * j4 + 1], h[4 * j4 + 2], h[4 * j4 + 3]);
    }
    __syncthreads();

    // second linear (16 outputs per thread, full 32-k, vectorized h)
    ull oA[8], oB[8];
    {
        const ull* bp = (const ull*)(b2s + go);
#pragma unroll
        for (int j = 0; j < 8; j++) { oA[j] = bp[j]; oB[j] = bp[j]; }
    }
#pragma unroll
    for (int k4 = 0; k4 < 8; k4++) {
        float4 hA4 = *(const float4*)(cs + eA * SP + 4 * k4);
        float4 hB4 = *(const float4*)(cs + eB * SP + 4 * k4);
        fma8p2_k4(oA, oB, hA4, hB4, &w2s[4 * k4 * 32 + go]);
    }

    float vA[16], vB[16];
#pragma unroll
    for (int j = 0; j < 8; j++) {
        unpack2(oA[j], vA[2 * j], vA[2 * j + 1]);
        unpack2(oB[j], vB[2 * j], vB[2 * j + 1]);
    }

    // scatter raw edge outputs to node sums (vectorized L2 reductions)
    {
        float* npA = nsum + (size_t)rA * 32 + go;
        float* npB = nsum + (size_t)rB * 32 + go;
#pragma unroll
        for (int j4 = 0; j4 < 4; j4++) {
            asm volatile("red.global.add.v4.f32 [%0], {%1,%2,%3,%4};"
                         :: "l"(npA + j4 * 4),
                            "f"(vA[j4 * 4 + 0]), "f"(vA[j4 * 4 + 1]),
                            "f"(vA[j4 * 4 + 2]), "f"(vA[j4 * 4 + 3])
                         : "memory");
        }
#pragma unroll
        for (int j4 = 0; j4 < 4; j4++) {
            asm volatile("red.global.add.v4.f32 [%0], {%1,%2,%3,%4};"
                         :: "l"(npB + j4 * 4),
                            "f"(vB[j4 * 4 + 0]), "f"(vB[j4 * 4 + 1]),
                            "f"(vB[j4 * 4 + 2]), "f"(vB[j4 * 4 + 3])
                         : "memory");
        }
    }

#pragma unroll
    for (int j = 0; j < 16; j++) { vA[j] = lrelu(vA[j]); vB[j] = lrelu(vB[j]); }

    // write edge-path values into cs cols [go,go+16)
    __syncthreads();   // all GEMM2 reads of cs complete
#pragma unroll
    for (int j4 = 0; j4 < 4; j4++) {
        *(float4*)(cs + eA * SP + go + 4 * j4) =
            make_float4(vA[4 * j4], vA[4 * j4 + 1], vA[4 * j4 + 2], vA[4 * j4 + 3]);
        *(float4*)(cs + eB * SP + go + 4 * j4) =
            make_float4(vB[4 * j4], vB[4 * j4 + 1], vB[4 * j4 + 2], vB[4 * j4 + 3]);
    }

    if constexpr (FUSE_MLP) {
        const float* mws[3] = { ms, ms + 1056, ms + 2112 };
        const float* mbs[3] = { ms + 1024, ms + 2080, ms + 3136 };
#pragma unroll
        for (int L = 0; L < 3; L++) {
            __syncthreads();               // inputs for this layer ready
            ull tA2[8], tB2[8];
            const ull* bp = (const ull*)(mbs[L] + go);
#pragma unroll
            for (int j = 0; j < 8; j++) { tA2[j] = bp[j]; tB2[j] = bp[j]; }
#pragma unroll
            for (int k4 = 0; k4 < 8; k4++) {
                float4 hA4 = *(const float4*)(cs + eA * SP + 4 * k4);
                float4 hB4 = *(const float4*)(cs + eB * SP + 4 * k4);
                fma8p2_k4(tA2, tB2, hA4, hB4, mws[L] + 4 * k4 * 32 + go);
            }
            __syncthreads();               // all reads done before overwrite
            float xA[16], xB[16];
#pragma unroll
            for (int j = 0; j < 8; j++) {
                float a0, a1, c0, c1;
                unpack2(tA2[j], a0, a1);
                unpack2(tB2[j], c0, c1);
                if (L < 2) { a0 = lrelu(a0); a1 = lrelu(a1); c0 = lrelu(c0); c1 = lrelu(c1); }
                xA[2 * j] = a0; xA[2 * j + 1] = a1;
                xB[2 * j] = c0; xB[2 * j + 1] = c1;
            }
#pragma unroll
            for (int j4 = 0; j4 < 4; j4++) {
                *(float4*)(cs + eA * SP + go + 4 * j4) =
                    make_float4(xA[4 * j4], xA[4 * j4 + 1], xA[4 * j4 + 2], xA[4 * j4 + 3]);
                *(float4*)(cs + eB * SP + go + 4 * j4) =
                    make_float4(xB[4 * j4], xB[4 * j4 + 1], xB[4 * j4 + 2], xB[4 * j4 + 3]);
            }
        }
    }

    // direct coalesced float4 store from edge-major buffer
    __syncthreads();
    float4* dst = (float4*)(eout + tile0 * 32);
#pragma unroll
    for (int it = 0; it < 8; it++) {
        int v = tid + it * 128;
        int eidx = v >> 3;
        int ch = (v & 7) * 4;
        dst[v] = *(const float4*)(cs + eidx * SP + ch);
    }
}

// ---------------- node-side kernels ----------------
__global__ void node_lr_kernel(const float* __restrict__ ns, float* __restrict__ nout) {
    int idx = blockIdx.x * 256 + threadIdx.x;     // grid sized exactly N*32/256
    float v = ns[idx] * g_inv[idx >> 5];
    nout[idx] = lrelu(v);
}

__global__ __launch_bounds__(256)
void node_final_kernel(const float* __restrict__ ns,
                       const float* __restrict__ nw1, const float* __restrict__ nb1,
                       const float* __restrict__ nw2, const float* __restrict__ nb2,
                       const float* __restrict__ nw3, const float* __restrict__ nb3,
                       float* __restrict__ out) {
    __shared__ float ws1[1024], ws2[1024], ws3[1024], bs1[32], bs2[32], bs3[32];
    int tid = threadIdx.x;
    for (int v = tid; v < 1024; v += 256) { ws1[v] = nw1[v]; ws2[v] = nw2[v]; ws3[v] = nw3[v]; }
    if (tid < 32) { bs1[tid] = nb1[tid]; bs2[tid] = nb2[tid]; bs3[tid] = nb3[tid]; }
    __syncthreads();

    int v = blockIdx.x * 256 + tid;
    if (v >= NNODE) return;

    float inv = g_inv[v];
    float x[32];
#pragma unroll
    for (int j4 = 0; j4 < 8; j4++) {
        float4 a = *(const float4*)(ns + (size_t)v * 32 + j4 * 4);
        x[j4 * 4 + 0] = lrelu(a.x * inv);
        x[j4 * 4 + 1] = lrelu(a.y * inv);
        x[j4 * 4 + 2] = lrelu(a.z * inv);
        x[j4 * 4 + 3] = lrelu(a.w * inv);
    }

    ull t2[16], u2[16];
    {
        const ull* bp = (const ull*)bs1;
#pragma unroll
        for (int j = 0; j < 16; j++) t2[j] = bp[j];
    }
#pragma unroll
    for (int k = 0; k < 32; k++) fma16p(t2, bcast2(x[k]), ws1 + k * 32);
#pragma unroll
    for (int j = 0; j < 16; j++) { float a0, a1; unpack2(t2[j], a0, a1); x[2 * j] = lrelu(a0); x[2 * j + 1] = lrelu(a1); }
    {
        const ull* bp = (const ull*)bs2;
#pragma unroll
        for (int j = 0; j < 16; j++) u2[j] = bp[j];
    }
#pragma unroll
    for (int k = 0; k < 32; k++) fma16p(u2, bcast2(x[k]), ws2 + k * 32);
#pragma unroll
    for (int j = 0; j < 16; j++) { float a0, a1; unpack2(u2[j], a0, a1); x[2 * j] = lrelu(a0); x[2 * j + 1] = lrelu(a1); }
    {
        const ull* bp = (const ull*)bs3;
#pragma unroll
        for (int j = 0; j < 16; j++) t2[j] = bp[j];
    }
#pragma unroll
    for (int k = 0; k < 32; k++) fma16p(t2, bcast2(x[k]), ws3 + k * 32);
#pragma unroll
    for (int j = 0; j < 16; j++) unpack2(t2[j], x[2 * j], x[2 * j + 1]);

    float* dst = out + (size_t)v * 32;
#pragma unroll
    for (int j4 = 0; j4 < 8; j4++) {
        float4 a = make_float4(x[j4 * 4 + 0], x[j4 * 4 + 1], x[j4 * 4 + 2], x[j4 * 4 + 3]);
        *(float4*)(dst + j4 * 4) = a;
    }
}

// ---------------- launch ----------------
extern "C" void kernel_launch(void* const* d_in, const int* in_sizes, int n_in,
                              void* d_out, int out_size) {
    const float* node_attr = (const float*)d_in[0];
    const float* edge_attr = (const float*)d_in[1];
    const int*   edge_index = (const int*)d_in[2];
    const float* c1w1 = (const float*)d_in[3];  const float* c1b1 = (const float*)d_in[4];
    const float* c1w2 = (const float*)d_in[5];  const float* c1b2 = (const float*)d_in[6];
    const float* c2w1 = (const float*)d_in[7];  const float* c2b1 = (const float*)d_in[8];
    const float* c2w2 = (const float*)d_in[9];  const float* c2b2 = (const float*)d_in[10];
    const float* c3w1 = (const float*)d_in[11]; const float* c3b1 = (const float*)d_in[12];
    const float* c3w2 = (const float*)d_in[13]; const float* c3b2 = (const float*)d_in[14];
    const float* nw1 = (const float*)d_in[15];  const float* nb1 = (const float*)d_in[16];
    const float* nw2 = (const float*)d_in[17];  const float* nb2 = (const float*)d_in[18];
    const float* nw3 = (const float*)d_in[19];  const float* nb3 = (const float*)d_in[20];
    const float* ew1 = (const float*)d_in[21];  const float* eb1 = (const float*)d_in[22];
    const float* ew2 = (const float*)d_in[23];  const float* eb2 = (const float*)d_in[24];
    const float* ew3 = (const float*)d_in[25];  const float* eb3 = (const float*)d_in[26];

    float* out_node = (float*)d_out;
    float* out_edge = out_node + (size_t)NNODE * 32;

    const int* row = edge_index;
    const int* col = edge_index + NEDGE;

    float *e1, *e2, *n1, *n2, *ns1, *ns2, *ns3;
    cudaGetSymbolAddress((void**)&e1, g_e1);
    cudaGetSymbolAddress((void**)&e2, g_e2);
    cudaGetSymbolAddress((void**)&n1, g_n1);
    cudaGetSymbolAddress((void**)&n2, g_n2);
    cudaGetSymbolAddress((void**)&ns1, g_ns1);
    cudaGetSymbolAddress((void**)&ns2, g_ns2);
    cudaGetSymbolAddress((void**)&ns3, g_ns3);

    // dynamic smem (floats): cs 128*36 | w1 CIN*32 | w2 1024 | b 64 | [ms 3168] | idx 256
    const int SM1 = (128 * 36 + 96 * 32 + 1024 + 64 + 256) * 4;             // 36096
    const int SM2 = (128 * 36 + 128 * 32 + 1024 + 64 + 256) * 4;            // 40192
    const int SM3 = (128 * 36 + 160 * 32 + 1024 + 64 + 3168 + 256) * 4;     // 56960
    cudaFuncSetAttribute(conv_kernel<96, false>,  cudaFuncAttributeMaxDynamicSharedMemorySize, SM1);
    cudaFuncSetAttribute(conv_kernel<128, false>, cudaFuncAttributeMaxDynamicSharedMemorySize, SM2);
    cudaFuncSetAttribute(conv_kernel<160, true>,  cudaFuncAttributeMaxDynamicSharedMemorySize, SM3);

    const int EB = NEDGE / 128;           // 12500 blocks, 128 edges each
    const int NB32 = NNODE * 32 / 256;    // 6250

    zero_kernel<<<1024, 256>>>();
    count_kernel<<<NEDGE / 256, 256>>>(row);
    inv_kernel<<<(NNODE + 255) / 256, 256>>>();

    conv_kernel<96, false><<<EB, 128, SM1>>>(
        node_attr, edge_attr, nullptr, nullptr, row, col,
        c1w1, c1b1, c1w2, c1b2,
        nullptr, nullptr, nullptr, nullptr, nullptr, nullptr,
        ns1, e1);
    node_lr_kernel<<<NB32, 256>>>(ns1, n1);

    conv_kernel<128, false><<<EB, 128, SM2>>>(
        n1, e1, edge_attr, nullptr, row, col,
        c2w1, c2b1, c2w2, c2b2,
        nullptr, nullptr, nullptr, nullptr, nullptr, nullptr,
        ns2, e2);
    node_lr_kernel<<<NB32, 256>>>(ns2, n2);

    conv_kernel<160, true><<<EB, 128, SM3>>>(
        n2, e2, e1, edge_attr, row, col,
        c3w1, c3b1, c3w2, c3b2,
        ew1, eb1, ew2, eb2, ew3, eb3,
        ns3, out_edge);

    node_final_kernel<<<(NNODE + 255) / 256, 256>>>(
        ns3, nw1, nb1, nw2, nb2, nw3, nb3, out_node);
}

// round 16
// speedup vs baseline: 1.1717x; 1.1717x over previous
#include <cuda_runtime.h>
#include <cstdint>

#define NNODE 50000
#define NEDGE 1600000

typedef unsigned long long ull;

// ---------------- device scratch (no allocations allowed) ----------------
__device__ float g_e1[(size_t)NEDGE * 32];
__device__ float g_e2[(size_t)NEDGE * 32];
__device__ float g_n1[(size_t)NNODE * 32];
__device__ float g_n2[(size_t)NNODE * 32];
__device__ float g_ns1[(size_t)NNODE * 32];
__device__ float g_ns2[(size_t)NNODE * 32];
__device__ float g_ns3[(size_t)NNODE * 32];
__device__ float g_inv[NNODE];
__device__ int   g_cnt[NNODE];

__device__ __forceinline__ float lrelu(float x) { return x > 0.f ? x : 0.2f * x; }

__device__ __forceinline__ ull bcast2(float v) {
    ull r; unsigned u = __float_as_uint(v);
    asm("mov.b64 %0, {%1,%1};" : "=l"(r) : "r"(u));
    return r;
}
__device__ __forceinline__ void unpack2(ull v, float& a, float& b) {
    unsigned lo, hi;
    asm("mov.b64 {%0,%1}, %2;" : "=r"(lo), "=r"(hi) : "l"(v));
    a = __uint_as_float(lo); b = __uint_as_float(hi);
}

// dual-edge, 16-output packed accumulate: one weight LDS.128 feeds 4 FFMA2
__device__ __forceinline__ void fma8p2(ull (&accA)[8], ull (&accB)[8],
                                       ull hA, ull hB,
                                       const float* __restrict__ wrow) {
    const ulonglong2* w = (const ulonglong2*)wrow;
#pragma unroll
    for (int j = 0; j < 4; j++) {
        ulonglong2 wv = w[j];
        asm("fma.rn.f32x2 %0, %1, %2, %0;" : "+l"(accA[2 * j + 0]) : "l"(hA), "l"(wv.x));
        asm("fma.rn.f32x2 %0, %1, %2, %0;" : "+l"(accB[2 * j + 0]) : "l"(hB), "l"(wv.x));
        asm("fma.rn.f32x2 %0, %1, %2, %0;" : "+l"(accA[2 * j + 1]) : "l"(hA), "l"(wv.y));
        asm("fma.rn.f32x2 %0, %1, %2, %0;" : "+l"(accB[2 * j + 1]) : "l"(hB), "l"(wv.y));
    }
}

__device__ __forceinline__ void fma8p2_k4(ull (&accA)[8], ull (&accB)[8],
                                          float4 hA4, float4 hB4,
                                          const float* __restrict__ wbase) {
    float hA[4] = { hA4.x, hA4.y, hA4.z, hA4.w };
    float hB[4] = { hB4.x, hB4.y, hB4.z, hB4.w };
#pragma unroll
    for (int q = 0; q < 4; q++)
        fma8p2(accA, accB, bcast2(hA[q]), bcast2(hB[q]), wbase + q * 32);
}

__device__ __forceinline__ void fma16p(ull (&acc)[16], ull h2, const float* __restrict__ wrow) {
    const ulonglong2* w = (const ulonglong2*)wrow;
#pragma unroll
    for (int j = 0; j < 8; j++) {
        ulonglong2 wv = w[j];
        asm("fma.rn.f32x2 %0, %1, %2, %0;" : "+l"(acc[2 * j + 0]) : "l"(h2), "l"(wv.x));
        asm("fma.rn.f32x2 %0, %1, %2, %0;" : "+l"(acc[2 * j + 1]) : "l"(h2), "l"(wv.y));
    }
}

// ---------------- setup kernels ----------------
__global__ void zero_kernel() {
    int stride = gridDim.x * blockDim.x;
    int i0 = blockIdx.x * blockDim.x + threadIdx.x;
    for (int v = i0; v < NNODE * 32; v += stride) {
        g_ns1[v] = 0.f; g_ns2[v] = 0.f; g_ns3[v] = 0.f;
    }
    for (int v = i0; v < NNODE; v += stride) g_cnt[v] = 0;
}

__global__ void count_kernel(const int* __restrict__ row) {
    int e = blockIdx.x * 256 + threadIdx.x;
    atomicAdd(&g_cnt[row[e]], 1);
}

__global__ void inv_kernel() {
    int v = blockIdx.x * 256 + threadIdx.x;
    if (v < NNODE) g_inv[v] = 1.f / fmaxf((float)g_cnt[v], 1.f);
}

// ---------------- fused edge-conv kernel ----------------
// 128 threads/block; each block processes T tiles of 128 edges (weights staged
// once per block). 6 blocks/SM for inter-block phase overlap.
// Thread layout: g = tid>>6 selects output half [g*16, g*16+16);
//                eA = tid&63, eB = eA+64 are the two edges this thread owns.
template <int CIN, bool FUSE_MLP, int T>
__global__ __launch_bounds__(128, 6)
void conv_kernel(const float* __restrict__ xn,
                 const float* __restrict__ ef0,
                 const float* __restrict__ ef1,
                 const float* __restrict__ ef2,
                 const int* __restrict__ ridx,
                 const int* __restrict__ cidx,
                 const float* __restrict__ w1, const float* __restrict__ b1,
                 const float* __restrict__ w2, const float* __restrict__ b2,
                 const float* __restrict__ mw1, const float* __restrict__ mb1,
                 const float* __restrict__ mw2, const float* __restrict__ mb2,
                 const float* __restrict__ mw3, const float* __restrict__ mb3,
                 float* __restrict__ nsum,
                 float* __restrict__ eout) {
    constexpr int NB = CIN / 32;
    constexpr int SP = 36;                 // floats per edge row
    constexpr int MSZ = FUSE_MLP ? 3168 : 0;
    extern __shared__ float sm[];
    float* cs  = sm;                       // 128 * 36
    float* w1s = sm + 128 * SP;            // CIN*32
    float* w2s = w1s + CIN * 32;           // 1024
    float* b1s = w2s + 1024;               // 32
    float* b2s = b1s + 32;                 // 32
    float* ms  = b2s + 32;                 // fused MLP weights
    int*   rs  = (int*)(ms + MSZ);         // 128
    int*   cls = rs + 128;                 // 128

    const int tid = threadIdx.x;           // 0..127
    const int g   = tid >> 6;
    const int go  = g * 16;
    const int eA  = tid & 63;
    const int eB  = eA + 64;

    // stage weights ONCE per block
    for (int v = tid; v < CIN * 32; v += 128) w1s[v] = w1[v];
    for (int v = tid; v < 1024; v += 128)     w2s[v] = w2[v];
    if (tid < 32) { b1s[tid] = b1[tid]; b2s[tid] = b2[tid]; }
    if constexpr (FUSE_MLP) {
        for (int v = tid; v < 1024; v += 128) {
            ms[v] = mw1[v]; ms[1056 + v] = mw2[v]; ms[2112 + v] = mw3[v];
        }
        if (tid < 32) { ms[1024 + tid] = mb1[tid]; ms[2080 + tid] = mb2[tid]; ms[3136 + tid] = mb3[tid]; }
    }

    const float* efp[3] = { ef0, ef1, ef2 };
    const int lane8 = tid & 7;             // 16B chunk within node row
    const int rowi  = tid >> 3;            // 0..15

    for (int t = 0; t < T; t++) {
        const size_t tile0 = ((size_t)blockIdx.x * T + t) * 128;

        rs[tid]  = ridx[tile0 + tid];
        cls[tid] = cidx[tile0 + tid];
        __syncthreads();                   // rs/cls ready; prev tile's cs reads done

        const int rA = rs[eA];
        const int rB = rs[eB];

        ull accA[8], accB[8];
        {
            const ull* bp = (const ull*)(b1s + go);
#pragma unroll
            for (int j = 0; j < 8; j++) { accA[j] = bp[j]; accB[j] = bp[j]; }
        }

        for (int b = 0; b < NB; b++) {
            if (b > 0) __syncthreads();    // compute of b-1 done before restage
            if (b < 2) {
                // vectorized gather: 8 lanes per 128B node row (4 rows/warp-inst)
                const int* sidx = (b == 0) ? rs : cls;
#pragma unroll
                for (int it = 0; it < 8; it++) {
                    int eidx = rowi + it * 16;
                    const float4* srcp = (const float4*)(xn + (size_t)sidx[eidx] * 32) + lane8;
                    *(float4*)(cs + eidx * SP + lane8 * 4) = *srcp;
                }
            } else {
                // direct float4 copy of 128x32 edge-feature chunk (edge-major)
                const float4* src = (const float4*)(efp[b - 2] + tile0 * 32);
#pragma unroll
                for (int it = 0; it < 8; it++) {
                    int v = tid + it * 128;
                    int eidx = v >> 3;
                    int ch = (v & 7) * 4;
                    *(float4*)(cs + eidx * SP + ch) = src[v];
                }
            }
            __syncthreads();
#pragma unroll
            for (int k4 = 0; k4 < 8; k4++) {
                float4 hA4 = *(const float4*)(cs + eA * SP + 4 * k4);
                float4 hB4 = *(const float4*)(cs + eB * SP + 4 * k4);
                fma8p2_k4(accA, accB, hA4, hB4, &w1s[(b * 32 + 4 * k4) * 32 + go]);
            }
        }

        // stage relu(hidden)
        __syncthreads();
        {
            float h[16];
#pragma unroll
            for (int j = 0; j < 8; j++) {
                float a0, a1; unpack2(accA[j], a0, a1);
                h[2 * j] = fmaxf(a0, 0.f); h[2 * j + 1] = fmaxf(a1, 0.f);
            }
#pragma unroll
            for (int j4 = 0; j4 < 4; j4++)
                *(float4*)(cs + eA * SP + go + 4 * j4) =
                    make_float4(h[4 * j4], h[4 * j4 + 1], h[4 * j4 + 2], h[4 * j4 + 3]);
#pragma unroll
            for (int j = 0; j < 8; j++) {
                float a0, a1; unpack2(accB[j], a0, a1);
                h[2 * j] = fmaxf(a0, 0.f); h[2 * j + 1] = fmaxf(a1, 0.f);
            }
#pragma unroll
            for (int j4 = 0; j4 < 4; j4++)
                *(float4*)(cs + eB * SP + go + 4 * j4) =
                    make_float4(h[4 * j4], h[4 * j4 + 1], h[4 * j4 + 2], h[4 * j4 + 3]);
        }
        __syncthreads();

        // second linear
        ull oA[8], oB[8];
        {
            const ull* bp = (const ull*)(b2s + go);
#pragma unroll
            for (int j = 0; j < 8; j++) { oA[j] = bp[j]; oB[j] = bp[j]; }
        }
#pragma unroll
        for (int k4 = 0; k4 < 8; k4++) {
            float4 hA4 = *(const float4*)(cs + eA * SP + 4 * k4);
            float4 hB4 = *(const float4*)(cs + eB * SP + 4 * k4);
            fma8p2_k4(oA, oB, hA4, hB4, &w2s[4 * k4 * 32 + go]);
        }

        float vA[16], vB[16];
#pragma unroll
        for (int j = 0; j < 8; j++) {
            unpack2(oA[j], vA[2 * j], vA[2 * j + 1]);
            unpack2(oB[j], vB[2 * j], vB[2 * j + 1]);
        }

        // scatter raw edge outputs to node sums
        {
            float* npA = nsum + (size_t)rA * 32 + go;
            float* npB = nsum + (size_t)rB * 32 + go;
#pragma unroll
            for (int j4 = 0; j4 < 4; j4++) {
                asm volatile("red.global.add.v4.f32 [%0], {%1,%2,%3,%4};"
                             :: "l"(npA + j4 * 4),
                                "f"(vA[j4 * 4 + 0]), "f"(vA[j4 * 4 + 1]),
                                "f"(vA[j4 * 4 + 2]), "f"(vA[j4 * 4 + 3])
                             : "memory");
            }
#pragma unroll
            for (int j4 = 0; j4 < 4; j4++) {
                asm volatile("red.global.add.v4.f32 [%0], {%1,%2,%3,%4};"
                             :: "l"(npB + j4 * 4),
                                "f"(vB[j4 * 4 + 0]), "f"(vB[j4 * 4 + 1]),
                                "f"(vB[j4 * 4 + 2]), "f"(vB[j4 * 4 + 3])
                             : "memory");
            }
        }

#pragma unroll
        for (int j = 0; j < 16; j++) { vA[j] = lrelu(vA[j]); vB[j] = lrelu(vB[j]); }

        __syncthreads();   // all GEMM2 reads of cs complete
#pragma unroll
        for (int j4 = 0; j4 < 4; j4++) {
            *(float4*)(cs + eA * SP + go + 4 * j4) =
                make_float4(vA[4 * j4], vA[4 * j4 + 1], vA[4 * j4 + 2], vA[4 * j4 + 3]);
            *(float4*)(cs + eB * SP + go + 4 * j4) =
                make_float4(vB[4 * j4], vB[4 * j4 + 1], vB[4 * j4 + 2], vB[4 * j4 + 3]);
        }

        if constexpr (FUSE_MLP) {
            const float* mws[3] = { ms, ms + 1056, ms + 2112 };
            const float* mbs[3] = { ms + 1024, ms + 2080, ms + 3136 };
#pragma unroll
            for (int L = 0; L < 3; L++) {
                __syncthreads();
                ull tA2[8], tB2[8];
                const ull* bp = (const ull*)(mbs[L] + go);
#pragma unroll
                for (int j = 0; j < 8; j++) { tA2[j] = bp[j]; tB2[j] = bp[j]; }
#pragma unroll
                for (int k4 = 0; k4 < 8; k4++) {
                    float4 hA4 = *(const float4*)(cs + eA * SP + 4 * k4);
                    float4 hB4 = *(const float4*)(cs + eB * SP + 4 * k4);
                    fma8p2_k4(tA2, tB2, hA4, hB4, mws[L] + 4 * k4 * 32 + go);
                }
                __syncthreads();
                float xA[16], xB[16];
#pragma unroll
                for (int j = 0; j < 8; j++) {
                    float a0, a1, c0, c1;
                    unpack2(tA2[j], a0, a1);
                    unpack2(tB2[j], c0, c1);
                    if (L < 2) { a0 = lrelu(a0); a1 = lrelu(a1); c0 = lrelu(c0); c1 = lrelu(c1); }
                    xA[2 * j] = a0; xA[2 * j + 1] = a1;
                    xB[2 * j] = c0; xB[2 * j + 1] = c1;
                }
#pragma unroll
                for (int j4 = 0; j4 < 4; j4++) {
                    *(float4*)(cs + eA * SP + go + 4 * j4) =
                        make_float4(xA[4 * j4], xA[4 * j4 + 1], xA[4 * j4 + 2], xA[4 * j4 + 3]);
                    *(float4*)(cs + eB * SP + go + 4 * j4) =
                        make_float4(xB[4 * j4], xB[4 * j4 + 1], xB[4 * j4 + 2], xB[4 * j4 + 3]);
                }
            }
        }

        // coalesced float4 store
        __syncthreads();
        float4* dst = (float4*)(eout + tile0 * 32);
#pragma unroll
        for (int it = 0; it < 8; it++) {
            int v = tid + it * 128;
            int eidx = v >> 3;
            int ch = (v & 7) * 4;
            dst[v] = *(const float4*)(cs + eidx * SP + ch);
        }
    }
}

// ---------------- node-side kernels ----------------
__global__ void node_lr_kernel(const float* __restrict__ ns, float* __restrict__ nout) {
    int idx = blockIdx.x * 256 + threadIdx.x;
    float v = ns[idx] * g_inv[idx >> 5];
    nout[idx] = lrelu(v);
}

__global__ __launch_bounds__(256)
void node_final_kernel(const float* __restrict__ ns,
                       const float* __restrict__ nw1, const float* __restrict__ nb1,
                       const float* __restrict__ nw2, const float* __restrict__ nb2,
                       const float* __restrict__ nw3, const float* __restrict__ nb3,
                       float* __restrict__ out) {
    __shared__ float ws1[1024], ws2[1024], ws3[1024], bs1[32], bs2[32], bs3[32];
    int tid = threadIdx.x;
    for (int v = tid; v < 1024; v += 256) { ws1[v] = nw1[v]; ws2[v] = nw2[v]; ws3[v] = nw3[v]; }
    if (tid < 32) { bs1[tid] = nb1[tid]; bs2[tid] = nb2[tid]; bs3[tid] = nb3[tid]; }
    __syncthreads();

    int v = blockIdx.x * 256 + tid;
    if (v >= NNODE) return;

    float inv = g_inv[v];
    float x[32];
#pragma unroll
    for (int j4 = 0; j4 < 8; j4++) {
        float4 a = *(const float4*)(ns + (size_t)v * 32 + j4 * 4);
        x[j4 * 4 + 0] = lrelu(a.x * inv);
        x[j4 * 4 + 1] = lrelu(a.y * inv);
        x[j4 * 4 + 2] = lrelu(a.z * inv);
        x[j4 * 4 + 3] = lrelu(a.w * inv);
    }

    ull t2[16], u2[16];
    {
        const ull* bp = (const ull*)bs1;
#pragma unroll
        for (int j = 0; j < 16; j++) t2[j] = bp[j];
    }
#pragma unroll
    for (int k = 0; k < 32; k++) fma16p(t2, bcast2(x[k]), ws1 + k * 32);
#pragma unroll
    for (int j = 0; j < 16; j++) { float a0, a1; unpack2(t2[j], a0, a1); x[2 * j] = lrelu(a0); x[2 * j + 1] = lrelu(a1); }
    {
        const ull* bp = (const ull*)bs2;
#pragma unroll
        for (int j = 0; j < 16; j++) u2[j] = bp[j];
    }
#pragma unroll
    for (int k = 0; k < 32; k++) fma16p(u2, bcast2(x[k]), ws2 + k * 32);
#pragma unroll
    for (int j = 0; j < 16; j++) { float a0, a1; unpack2(u2[j], a0, a1); x[2 * j] = lrelu(a0); x[2 * j + 1] = lrelu(a1); }
    {
        const ull* bp = (const ull*)bs3;
#pragma unroll
        for (int j = 0; j < 16; j++) t2[j] = bp[j];
    }
#pragma unroll
    for (int k = 0; k < 32; k++) fma16p(t2, bcast2(x[k]), ws3 + k * 32);
#pragma unroll
    for (int j = 0; j < 16; j++) unpack2(t2[j], x[2 * j], x[2 * j + 1]);

    float* dst = out + (size_t)v * 32;
#pragma unroll
    for (int j4 = 0; j4 < 8; j4++) {
        float4 a = make_float4(x[j4 * 4 + 0], x[j4 * 4 + 1], x[j4 * 4 + 2], x[j4 * 4 + 3]);
        *(float4*)(dst + j4 * 4) = a;
    }
}

// ---------------- launch ----------------
extern "C" void kernel_launch(void* const* d_in, const int* in_sizes, int n_in,
                              void* d_out, int out_size) {
    const float* node_attr = (const float*)d_in[0];
    const float* edge_attr = (const float*)d_in[1];
    const int*   edge_index = (const int*)d_in[2];
    const float* c1w1 = (const float*)d_in[3];  const float* c1b1 = (const float*)d_in[4];
    const float* c1w2 = (const float*)d_in[5];  const float* c1b2 = (const float*)d_in[6];
    const float* c2w1 = (const float*)d_in[7];  const float* c2b1 = (const float*)d_in[8];
    const float* c2w2 = (const float*)d_in[9];  const float* c2b2 = (const float*)d_in[10];
    const float* c3w1 = (const float*)d_in[11]; const float* c3b1 = (const float*)d_in[12];
    const float* c3w2 = (const float*)d_in[13]; const float* c3b2 = (const float*)d_in[14];
    const float* nw1 = (const float*)d_in[15];  const float* nb1 = (const float*)d_in[16];
    const float* nw2 = (const float*)d_in[17];  const float* nb2 = (const float*)d_in[18];
    const float* nw3 = (const float*)d_in[19];  const float* nb3 = (const float*)d_in[20];
    const float* ew1 = (const float*)d_in[21];  const float* eb1 = (const float*)d_in[22];
    const float* ew2 = (const float*)d_in[23];  const float* eb2 = (const float*)d_in[24];
    const float* ew3 = (const float*)d_in[25];  const float* eb3 = (const float*)d_in[26];

    float* out_node = (float*)d_out;
    float* out_edge = out_node + (size_t)NNODE * 32;

    const int* row = edge_index;
    const int* col = edge_index + NEDGE;

    float *e1, *e2, *n1, *n2, *ns1, *ns2, *ns3;
    cudaGetSymbolAddress((void**)&e1, g_e1);
    cudaGetSymbolAddress((void**)&e2, g_e2);
    cudaGetSymbolAddress((void**)&n1, g_n1);
    cudaGetSymbolAddress((void**)&n2, g_n2);
    cudaGetSymbolAddress((void**)&ns1, g_ns1);
    cudaGetSymbolAddress((void**)&ns2, g_ns2);
    cudaGetSymbolAddress((void**)&ns3, g_ns3);

    const int SM1 = (128 * 36 + 96 * 32 + 1024 + 64 + 256) * 4;             // 36096
    const int SM2 = (128 * 36 + 128 * 32 + 1024 + 64 + 256) * 4;            // 40192
    const int SM3 = (128 * 36 + 160 * 32 + 1024 + 64 + 3168 + 256) * 4;     // 56960
    cudaFuncSetAttribute(conv_kernel<96, false, 5>,  cudaFuncAttributeMaxDynamicSharedMemorySize, SM1);
    cudaFuncSetAttribute(conv_kernel<128, false, 5>, cudaFuncAttributeMaxDynamicSharedMemorySize, SM2);
    cudaFuncSetAttribute(conv_kernel<160, true, 5>,  cudaFuncAttributeMaxDynamicSharedMemorySize, SM3);

    const int EB = NEDGE / (128 * 5);     // 2500 blocks, 5 tiles of 128 edges each
    const int NB32 = NNODE * 32 / 256;    // 6250

    zero_kernel<<<1024, 256>>>();
    count_kernel<<<NEDGE / 256, 256>>>(row);
    inv_kernel<<<(NNODE + 255) / 256, 256>>>();

    conv_kernel<96, false, 5><<<EB, 128, SM1>>>(
        node_attr, edge_attr, nullptr, nullptr, row, col,
        c1w1, c1b1, c1w2, c1b2,
        nullptr, nullptr, nullptr, nullptr, nullptr, nullptr,
        ns1, e1);
    node_lr_kernel<<<NB32, 256>>>(ns1, n1);

    conv_kernel<128, false, 5><<<EB, 128, SM2>>>(
        n1, e1, edge_attr, nullptr, row, col,
        c2w1, c2b1, c2w2, c2b2,
        nullptr, nullptr, nullptr, nullptr, nullptr, nullptr,
        ns2, e2);
    node_lr_kernel<<<NB32, 256>>>(ns2, n2);

    conv_kernel<160, true, 5><<<EB, 128, SM3>>>(
        n2, e2, e1, edge_attr, row, col,
        c3w1, c3b1, c3w2, c3b2,
        ew1, eb1, ew2, eb2, ew3, eb3,
        ns3, out_edge);

    node_final_kernel<<<(NNODE + 255) / 256, 256>>>(
        ns3, nw1, nb1, nw2, nb2, nw3, nb3, out_node);
}